// round 9
// baseline (speedup 1.0000x reference)
#include <cuda_runtime.h>
#include <math.h>

#define ROWS     512
#define NBASIS   256
#define RGRID    1024
#define QS       2048
#define NSLOTS   128
#define COLS_IN  512
#define SLOT_ELEMS (ROWS * RGRID)          // 524288
#define SLOT4      (SLOT_ELEMS / 4)        // 131072 = 2^17
#define TILE4    4096                      // float4 per stolen tile (64 KB)
#define TILES_PER_SLOT (SLOT4 / TILE4)     // 32
#define NTILES   (126 * TILES_PER_SLOT)    // 4032 (slots 2..127)

// K = sqrt(0.5 * log2(e)) / H,  H = 0.1
#define KSCALE   8.49321999f
// 1 / (B * H * sqrt(2*pi))
#define INV_NORM 0.0155836865f
// window cut in K-scaled units: exp2(-CUT^2) ~ 2e-13
#define CUT      6.5f

__device__ unsigned int g_tile = 0;
__device__ unsigned int g_done = 0;

__device__ __forceinline__ float fwd_y(float s, int sl) {
    switch (sl) {
        case 0: return 2.0f * s;
        case 1: return s - 3.0f;
        case 2: { float ss = (fabsf(s) < 1e-6f) ? 1e-6f : s; return 1.0f / ss; }
        case 3: return 0.8f * s + 5.0f;
        case 4: {
            if (s >= 0.0f) { float e = expf(-s); return 1.0f / (1.0f + e); }
            else           { float e = expf(s);  return e / (1.0f + e); }
        }
        default: // softplus, stable
            return fmaxf(s, 0.0f) + log1pf(expf(-fabsf(s)));
    }
}

__device__ __forceinline__ float ex2f_raw(float a) {
    float r;
    asm("ex2.approx.ftz.f32 %0, %1;" : "=f"(r) : "f"(a));
    return r;
}

// Even blocks: fused stats + pdf compute for (row, type) [R6 shape].
// ALL blocks then steal 64KB copy tiles from a global counter until drained.
__global__ __launch_bounds__(256) void main_kernel(
    const float* __restrict__ inputs,
    const float* __restrict__ bank,
    const float* __restrict__ noise,
    const int*   __restrict__ comp_idx,
    const int*   __restrict__ sel,
    const int*   __restrict__ slot_p,
    float*       __restrict__ out)
{
    int slot_idx = slot_p ? __ldg(slot_p) : 37;
    int bid = blockIdx.x;
    int t   = threadIdx.x;

    __shared__ float xsK[NBASIS];
    __shared__ float red[2][8];
    __shared__ float mnmx[2];
    __shared__ unsigned int s_tile;

    if ((bid & 1) == 0) {
        // ---------- compute part ----------
        int cid  = bid >> 1;        // 0..1023
        int row  = cid >> 1;        // 0..511
        int type = cid & 1;         // 0 = current, 1 = transformed

        xsK[t] = __ldg(&inputs[(size_t)t * COLS_IN + row]);   // raw basis
        __syncthreads();

        int sl = (type == 1) ? __ldg(&sel[row]) : -1;

        // fused stats: this block's own extreme (s for type0 / y for type1)
        {
            const float* nzr = noise    + (size_t)row * QS;
            const int*   cir = comp_idx + (size_t)row * QS;

            float emn =  INFINITY, emx = -INFINITY;
            bool  recip = (type == 1 && sl == 2);

            #pragma unroll
            for (int i = 0; i < 8; i++) {
                int q = t + i * 256;
                int c = __ldg(&cir[q]);
                float sv = xsK[c] + 0.1f * __ldg(&nzr[q]);
                if (recip) {
                    float ss = (fabsf(sv) < 1e-6f) ? 1e-6f : sv;
                    float y = 1.0f / ss;
                    emn = fminf(emn, y);  emx = fmaxf(emx, y);
                } else {
                    emn = fminf(emn, sv); emx = fmaxf(emx, sv);
                }
            }
            #pragma unroll
            for (int o = 16; o > 0; o >>= 1) {
                emn = fminf(emn, __shfl_xor_sync(0xffffffffu, emn, o));
                emx = fmaxf(emx, __shfl_xor_sync(0xffffffffu, emx, o));
            }
            int w = t >> 5;
            if ((t & 31) == 0) { red[0][w] = emn; red[1][w] = emx; }
            __syncthreads();
            if (t == 0) {
                float a = red[0][0], b = red[1][0];
                #pragma unroll
                for (int i = 1; i < 8; i++) {
                    a = fminf(a, red[0][i]); b = fmaxf(b, red[1][i]);
                }
                if (type == 1 && sl != 2) { a = fwd_y(a, sl); b = fwd_y(b, sl); }
                mnmx[0] = a; mnmx[1] = b;
            }
        }

        // scale basis in place, then sort
        __syncthreads();
        float scaled = xsK[t] * KSCALE;
        __syncthreads();
        xsK[t] = scaled;
        __syncthreads();

        // bitonic sort xsK ascending
        #pragma unroll
        for (int k = 2; k <= NBASIS; k <<= 1) {
            for (int j = k >> 1; j > 0; j >>= 1) {
                int ixj = t ^ j;
                if (ixj > t) {
                    float a = xsK[t], b = xsK[ixj];
                    bool up = ((t & k) == 0);
                    if ((a > b) == up) { xsK[t] = b; xsK[ixj] = a; }
                }
                __syncthreads();
            }
        }

        float mn = mnmx[0], mx = mnmx[1];
        float span = mx - mn;

        // 4 consecutive grid points per thread
        float u[4], lf[4];
        float umn =  INFINITY, umx = -INFINITY;
        #pragma unroll
        for (int i = 0; i < 4; i++) {
            int j = 4 * t + i;
            float frac = (float)j / 1023.0f;
            float tg = mn + span * frac;
            if (tg == 0.0f) tg = 1e-7f;
            float xi, l;
            if (type == 0) { xi = tg; l = 1.0f; }
            else {
                switch (sl) {
                    case 0: xi = tg * 0.5f;          l = 0.5f;  break;
                    case 1: xi = tg + 3.0f;          l = 1.0f;  break;
                    case 2: xi = 1.0f / tg;          l = 1.0f / (tg * tg); break;
                    case 3: xi = (tg - 5.0f) / 0.8f; l = 1.25f; break;
                    case 4: {
                        float yc = fminf(fmaxf(tg, 1e-6f), 1.0f - 1e-6f);
                        xi = logf(yc) - log1pf(-yc);
                        l  = 1.0f / (yc * (1.0f - yc));
                        break;
                    }
                    default: {
                        float yp = fmaxf(tg, 1e-6f);
                        float em = expm1f(yp);
                        xi = logf(em);
                        l  = 1.0f / (-expm1f(-yp));
                        break;
                    }
                }
            }
            float uv = xi * KSCALE;
            u[i]  = uv;
            lf[i] = l;
            umn = fminf(umn, uv);
            umx = fmaxf(umx, uv);
        }

        // warp-union window
        #pragma unroll
        for (int o = 16; o > 0; o >>= 1) {
            umn = fminf(umn, __shfl_xor_sync(0xffffffffu, umn, o));
            umx = fmaxf(umx, __shfl_xor_sync(0xffffffffu, umx, o));
        }
        float lowv  = umn - CUT;
        float highv = umx + CUT;

        int lo, hi;
        { int l = 0, r = NBASIS;
          while (l < r) { int m = (l + r) >> 1; if (xsK[m] < lowv)   l = m + 1; else r = m; }
          lo = l; }
        { int l = lo, r = NBASIS;
          while (l < r) { int m = (l + r) >> 1; if (xsK[m] <= highv) l = m + 1; else r = m; }
          hi = l; }

        float a0 = 0.f, a1 = 0.f, a2 = 0.f, a3 = 0.f;
        for (int b = lo; b < hi; b++) {
            float xv = xsK[b];                   // broadcast LDS
            float d0 = u[0] - xv;
            float d1 = u[1] - xv;
            float d2 = u[2] - xv;
            float d3 = u[3] - xv;
            a0 += ex2f_raw(-d0 * d0);
            a1 += ex2f_raw(-d1 * d1);
            a2 += ex2f_raw(-d2 * d2);
            a3 += ex2f_raw(-d3 * d3);
        }

        if (slot_idx != type) {
            float4 v;
            v.x = (a0 == 0.f) ? 0.f : a0 * INV_NORM * lf[0];
            v.y = (a1 == 0.f) ? 0.f : a1 * INV_NORM * lf[1];
            v.z = (a2 == 0.f) ? 0.f : a2 * INV_NORM * lf[2];
            v.w = (a3 == 0.f) ? 0.f : a3 * INV_NORM * lf[3];
            float4* dst = (float4*)(out + (size_t)type * SLOT_ELEMS + (size_t)row * RGRID);
            dst[t] = v;
        }
        __syncthreads();   // everyone done with smem before stealing loop reuses s_tile
    }

    // ---------- work-stealing copy: all blocks ----------
    const float4* __restrict__ bank4 = (const float4*)bank;
    float4*       __restrict__ out4  = (float4*)out;

    for (;;) {
        if (t == 0) s_tile = atomicAdd(&g_tile, 1u);
        __syncthreads();
        unsigned int tt = s_tile;
        __syncthreads();
        if (tt >= NTILES) break;

        int s    = (int)(tt / TILES_PER_SLOT) + 2;        // slot 2..127
        long off = (long)(tt % TILES_PER_SLOT) * TILE4;
        int srcs = (s == slot_idx) ? 0 : s;

        const float4* __restrict__ src = bank4 + (long)srcs * SLOT4 + off;
        float4*       __restrict__ dst = out4  + (long)s    * SLOT4 + off;

        #pragma unroll 8
        for (int i = t; i < TILE4; i += 256) {
            dst[i] = src[i];
        }
    }

    // ---------- self-reset of counters (last block) ----------
    if (t == 0) {
        __threadfence();
        unsigned int d = atomicAdd(&g_done, 1u);
        if (d == gridDim.x - 1) {
            g_tile = 0u;
            __threadfence();
            g_done = 0u;
        }
    }
}

extern "C" void kernel_launch(void* const* d_in, const int* in_sizes, int n_in,
                              void* d_out, int out_size)
{
    const float* inputs   = (const float*)d_in[0];
    const float* bank     = (const float*)d_in[1];
    const float* noise    = (const float*)d_in[2];
    const int*   comp_idx = (const int*)  d_in[3];
    const int*   sel      = (const int*)  d_in[4];
    const int*   slot_p   = (n_in >= 6) ? (const int*)d_in[5] : nullptr;
    float* out = (float*)d_out;

    main_kernel<<<2048, 256>>>(inputs, bank, noise, comp_idx, sel, slot_p, out);
}

// round 10
// speedup vs baseline: 1.1499x; 1.1499x over previous
#include <cuda_runtime.h>
#include <math.h>

#define ROWS     512
#define NBASIS   256
#define RGRID    1024
#define QS       2048
#define NSLOTS   128
#define COLS_IN  512
#define SLOT_ELEMS (ROWS * RGRID)          // 524288
#define SLOT4      (SLOT_ELEMS / 4)        // 131072 = 2^17
#define CHUNK4   16384                     // float4 per copy block (8 blocks/slot)

// K = sqrt(0.5 * log2(e)) / H,  H = 0.1
#define KSCALE   8.49321999f
// 1 / (B * H * sqrt(2*pi))
#define INV_NORM 0.0155836865f
// window cut in K-scaled units: exp2(-CUT^2) ~ 2e-13
#define CUT      6.5f

__device__ __forceinline__ float fwd_y(float s, int sl) {
    switch (sl) {
        case 0: return 2.0f * s;
        case 1: return s - 3.0f;
        case 2: { float ss = (fabsf(s) < 1e-6f) ? 1e-6f : s; return 1.0f / ss; }
        case 3: return 0.8f * s + 5.0f;
        case 4: {
            if (s >= 0.0f) { float e = expf(-s); return 1.0f / (1.0f + e); }
            else           { float e = expf(s);  return e / (1.0f + e); }
        }
        default: // softplus, stable
            return fmaxf(s, 0.0f) + log1pf(expf(-fabsf(s)));
    }
}

__device__ __forceinline__ float ex2f_raw(float a) {
    float r;
    asm("ex2.approx.ftz.f32 %0, %1;" : "=f"(r) : "f"(a));
    return r;
}

// bid <  1024 : contiguous-chunk bank->out copy (launches first, saturates DRAM).
// bid >= 1024 : fused stats + pdf compute for (row, type), window-pruned.
__global__ __launch_bounds__(256) void main_kernel(
    const float* __restrict__ inputs,
    const float* __restrict__ bank,
    const float* __restrict__ noise,
    const int*   __restrict__ comp_idx,
    const int*   __restrict__ sel,
    const int*   __restrict__ slot_p,
    float*       __restrict__ out)
{
    int slot_idx = slot_p ? __ldg(slot_p) : 37;
    int bid = blockIdx.x;
    int t   = threadIdx.x;

    if (bid < 1024) {
        // ---------- copy branch: one contiguous chunk per block ----------
        int cb = bid;               // 0..1023
        int s  = cb >> 3;           // slot 0..127 (8 blocks per slot)
        int srcs;
        if (s == slot_idx)      srcs = 0;      // out[slot_idx] = prev = bank[0]
        else if (s < 2)         return;        // slots 0/1 written by compute blocks
        else                    srcs = s;

        long coff = (long)(cb & 7) * CHUNK4;
        const float4* __restrict__ src = (const float4*)bank + (long)srcs * SLOT4 + coff;
        float4*       __restrict__ dst = (float4*)out        + (long)s    * SLOT4 + coff;

        #pragma unroll 8
        for (int i = t; i < CHUNK4; i += 256) {
            dst[i] = src[i];
        }
    } else {
        // ---------- compute branch ----------
        int cid  = bid - 1024;      // 0..1023
        int row  = cid >> 1;        // 0..511
        int type = cid & 1;         // 0 = current, 1 = transformed

        __shared__ float xsRaw[NBASIS];   // raw basis (gather, bit-exact)
        __shared__ float xsK[NBASIS];     // scaled basis (sorted, MUFU)
        __shared__ float red[2][8];
        __shared__ float mnmx[2];

        {
            float raw = __ldg(&inputs[(size_t)t * COLS_IN + row]);
            xsRaw[t] = raw;
            xsK[t]   = raw * KSCALE;
        }
        __syncthreads();

        int sl = (type == 1) ? __ldg(&sel[row]) : -1;

        // ---- fused stats: this block's own extreme (s for type0 / y for type1) ----
        {
            const int4*   cir4 = (const int4*)  (comp_idx + (size_t)row * QS);
            const float4* nzr4 = (const float4*)(noise    + (size_t)row * QS);

            float emn =  INFINITY, emx = -INFINITY;
            bool  recip = (type == 1 && sl == 2);

            #pragma unroll
            for (int i = 0; i < 2; i++) {
                int4   c4 = __ldg(&cir4[t + i * 256]);
                float4 n4 = __ldg(&nzr4[t + i * 256]);
                float sv0 = xsRaw[c4.x] + 0.1f * n4.x;
                float sv1 = xsRaw[c4.y] + 0.1f * n4.y;
                float sv2 = xsRaw[c4.z] + 0.1f * n4.z;
                float sv3 = xsRaw[c4.w] + 0.1f * n4.w;
                if (recip) {
                    float s0 = (fabsf(sv0) < 1e-6f) ? 1e-6f : sv0;
                    float s1 = (fabsf(sv1) < 1e-6f) ? 1e-6f : sv1;
                    float s2 = (fabsf(sv2) < 1e-6f) ? 1e-6f : sv2;
                    float s3 = (fabsf(sv3) < 1e-6f) ? 1e-6f : sv3;
                    float y0 = 1.0f / s0, y1 = 1.0f / s1, y2 = 1.0f / s2, y3 = 1.0f / s3;
                    emn = fminf(emn, fminf(fminf(y0, y1), fminf(y2, y3)));
                    emx = fmaxf(emx, fmaxf(fmaxf(y0, y1), fmaxf(y2, y3)));
                } else {
                    emn = fminf(emn, fminf(fminf(sv0, sv1), fminf(sv2, sv3)));
                    emx = fmaxf(emx, fmaxf(fmaxf(sv0, sv1), fmaxf(sv2, sv3)));
                }
            }
            #pragma unroll
            for (int o = 16; o > 0; o >>= 1) {
                emn = fminf(emn, __shfl_xor_sync(0xffffffffu, emn, o));
                emx = fmaxf(emx, __shfl_xor_sync(0xffffffffu, emx, o));
            }
            int w = t >> 5;
            if ((t & 31) == 0) { red[0][w] = emn; red[1][w] = emx; }
            __syncthreads();
            if (t == 0) {
                float a = red[0][0], b = red[1][0];
                #pragma unroll
                for (int i = 1; i < 8; i++) {
                    a = fminf(a, red[0][i]); b = fmaxf(b, red[1][i]);
                }
                if (type == 1 && sl != 2) { a = fwd_y(a, sl); b = fwd_y(b, sl); }
                mnmx[0] = a; mnmx[1] = b;
            }
        }
        __syncthreads();

        // ---- bitonic sort xsK ascending ----
        #pragma unroll
        for (int k = 2; k <= NBASIS; k <<= 1) {
            for (int j = k >> 1; j > 0; j >>= 1) {
                int ixj = t ^ j;
                if (ixj > t) {
                    float a = xsK[t], b = xsK[ixj];
                    bool up = ((t & k) == 0);
                    if ((a > b) == up) { xsK[t] = b; xsK[ixj] = a; }
                }
                __syncthreads();
            }
        }

        float mn = mnmx[0], mx = mnmx[1];
        float span = mx - mn;

        // ---- 4 consecutive grid points per thread ----
        float u[4], lf[4];
        float umn =  INFINITY, umx = -INFINITY;
        #pragma unroll
        for (int i = 0; i < 4; i++) {
            int j = 4 * t + i;
            float frac = (float)j / 1023.0f;
            float tg = mn + span * frac;
            if (tg == 0.0f) tg = 1e-7f;
            float xi, l;
            if (type == 0) { xi = tg; l = 1.0f; }
            else {
                switch (sl) {
                    case 0: xi = tg * 0.5f;          l = 0.5f;  break;
                    case 1: xi = tg + 3.0f;          l = 1.0f;  break;
                    case 2: xi = 1.0f / tg;          l = 1.0f / (tg * tg); break;
                    case 3: xi = (tg - 5.0f) / 0.8f; l = 1.25f; break;
                    case 4: {
                        float yc = fminf(fmaxf(tg, 1e-6f), 1.0f - 1e-6f);
                        xi = logf(yc) - log1pf(-yc);
                        l  = 1.0f / (yc * (1.0f - yc));
                        break;
                    }
                    default: {
                        float yp = fmaxf(tg, 1e-6f);
                        float em = expm1f(yp);
                        xi = logf(em);
                        l  = 1.0f / (-expm1f(-yp));
                        break;
                    }
                }
            }
            float uv = xi * KSCALE;
            u[i]  = uv;
            lf[i] = l;
            umn = fminf(umn, uv);
            umx = fmaxf(umx, uv);
        }

        // ---- warp-union window ----
        #pragma unroll
        for (int o = 16; o > 0; o >>= 1) {
            umn = fminf(umn, __shfl_xor_sync(0xffffffffu, umn, o));
            umx = fmaxf(umx, __shfl_xor_sync(0xffffffffu, umx, o));
        }
        float lowv  = umn - CUT;
        float highv = umx + CUT;

        int lo, hi;
        { int l = 0, r = NBASIS;
          while (l < r) { int m = (l + r) >> 1; if (xsK[m] < lowv)   l = m + 1; else r = m; }
          lo = l; }
        { int l = lo, r = NBASIS;
          while (l < r) { int m = (l + r) >> 1; if (xsK[m] <= highv) l = m + 1; else r = m; }
          hi = l; }

        float a0 = 0.f, a1 = 0.f, a2 = 0.f, a3 = 0.f;
        for (int b = lo; b < hi; b++) {
            float xv = xsK[b];                   // broadcast LDS
            float d0 = u[0] - xv;
            float d1 = u[1] - xv;
            float d2 = u[2] - xv;
            float d3 = u[3] - xv;
            a0 += ex2f_raw(-d0 * d0);
            a1 += ex2f_raw(-d1 * d1);
            a2 += ex2f_raw(-d2 * d2);
            a3 += ex2f_raw(-d3 * d3);
        }

        if (slot_idx != type) {
            float4 v;
            v.x = (a0 == 0.f) ? 0.f : a0 * INV_NORM * lf[0];
            v.y = (a1 == 0.f) ? 0.f : a1 * INV_NORM * lf[1];
            v.z = (a2 == 0.f) ? 0.f : a2 * INV_NORM * lf[2];
            v.w = (a3 == 0.f) ? 0.f : a3 * INV_NORM * lf[3];
            float4* dst = (float4*)(out + (size_t)type * SLOT_ELEMS + (size_t)row * RGRID);
            dst[t] = v;
        }
    }
}

extern "C" void kernel_launch(void* const* d_in, const int* in_sizes, int n_in,
                              void* d_out, int out_size)
{
    const float* inputs   = (const float*)d_in[0];
    const float* bank     = (const float*)d_in[1];
    const float* noise    = (const float*)d_in[2];
    const int*   comp_idx = (const int*)  d_in[3];
    const int*   sel      = (const int*)  d_in[4];
    const int*   slot_p   = (n_in >= 6) ? (const int*)d_in[5] : nullptr;
    float* out = (float*)d_out;

    main_kernel<<<2048, 256>>>(inputs, bank, noise, comp_idx, sel, slot_p, out);
}

// round 11
// speedup vs baseline: 1.2265x; 1.0666x over previous
#include <cuda_runtime.h>
#include <math.h>

#define ROWS     512
#define NBASIS   256
#define RGRID    1024
#define QS       2048
#define NSLOTS   128
#define COLS_IN  512
#define SLOT_ELEMS (ROWS * RGRID)          // 524288
#define SLOT4      (SLOT_ELEMS / 4)        // 131072
#define CHUNK4   16384                     // float4 per copy block (8 blocks/slot)

// K = sqrt(0.5 * log2(e)) / H,  H = 0.1
#define KSCALE   8.49321999f
// 1 / (B * H * sqrt(2*pi))
#define INV_NORM 0.0155836865f
// window cut in K-scaled units: exp2(-CUT^2) ~ 2e-13
#define CUT      6.5f

__device__ __forceinline__ float fwd_y(float s, int sl) {
    switch (sl) {
        case 0: return 2.0f * s;
        case 1: return s - 3.0f;
        case 2: { float ss = (fabsf(s) < 1e-6f) ? 1e-6f : s; return 1.0f / ss; }
        case 3: return 0.8f * s + 5.0f;
        case 4: {
            if (s >= 0.0f) { float e = expf(-s); return 1.0f / (1.0f + e); }
            else           { float e = expf(s);  return e / (1.0f + e); }
        }
        default: // softplus, stable
            return fmaxf(s, 0.0f) + log1pf(expf(-fabsf(s)));
    }
}

__device__ __forceinline__ float ex2f_raw(float a) {
    float r;
    asm("ex2.approx.ftz.f32 %0, %1;" : "=f"(r) : "f"(a));
    return r;
}

// Even blocks: fused stats + pdf compute for (row, type); NO sort —
// warp-uniform window skip over the unsorted basis.
// Odd blocks: contiguous-chunk bank->out copy (plain LDG/STG.128).
__global__ __launch_bounds__(256) void main_kernel(
    const float* __restrict__ inputs,
    const float* __restrict__ bank,
    const float* __restrict__ noise,
    const int*   __restrict__ comp_idx,
    const int*   __restrict__ sel,
    const int*   __restrict__ slot_p,
    float*       __restrict__ out)
{
    int slot_idx = slot_p ? __ldg(slot_p) : 37;
    int bid = blockIdx.x;
    int t   = threadIdx.x;

    if ((bid & 1) == 0) {
        // ---------- compute branch ----------
        int cid  = bid >> 1;        // 0..1023
        int row  = cid >> 1;        // 0..511
        int type = cid & 1;         // 0 = current, 1 = transformed

        __shared__ float xsRaw[NBASIS];   // raw basis (gather, bit-exact)
        __shared__ float xsK[NBASIS];     // scaled basis (pdf loop)
        __shared__ float red[2][8];
        __shared__ float mnmx[2];

        {
            float raw = __ldg(&inputs[(size_t)t * COLS_IN + row]);
            xsRaw[t] = raw;
            xsK[t]   = raw * KSCALE;
        }
        __syncthreads();

        int sl = (type == 1) ? __ldg(&sel[row]) : -1;

        // ---- fused stats: this block's own extreme (s for type0 / y for type1) ----
        {
            const int4*   cir4 = (const int4*)  (comp_idx + (size_t)row * QS);
            const float4* nzr4 = (const float4*)(noise    + (size_t)row * QS);

            float emn =  INFINITY, emx = -INFINITY;
            bool  recip = (type == 1 && sl == 2);

            #pragma unroll
            for (int i = 0; i < 2; i++) {
                int4   c4 = __ldg(&cir4[t + i * 256]);
                float4 n4 = __ldg(&nzr4[t + i * 256]);
                float sv0 = xsRaw[c4.x] + 0.1f * n4.x;
                float sv1 = xsRaw[c4.y] + 0.1f * n4.y;
                float sv2 = xsRaw[c4.z] + 0.1f * n4.z;
                float sv3 = xsRaw[c4.w] + 0.1f * n4.w;
                if (recip) {
                    float s0 = (fabsf(sv0) < 1e-6f) ? 1e-6f : sv0;
                    float s1 = (fabsf(sv1) < 1e-6f) ? 1e-6f : sv1;
                    float s2 = (fabsf(sv2) < 1e-6f) ? 1e-6f : sv2;
                    float s3 = (fabsf(sv3) < 1e-6f) ? 1e-6f : sv3;
                    float y0 = 1.0f / s0, y1 = 1.0f / s1, y2 = 1.0f / s2, y3 = 1.0f / s3;
                    emn = fminf(emn, fminf(fminf(y0, y1), fminf(y2, y3)));
                    emx = fmaxf(emx, fmaxf(fmaxf(y0, y1), fmaxf(y2, y3)));
                } else {
                    emn = fminf(emn, fminf(fminf(sv0, sv1), fminf(sv2, sv3)));
                    emx = fmaxf(emx, fmaxf(fmaxf(sv0, sv1), fmaxf(sv2, sv3)));
                }
            }
            #pragma unroll
            for (int o = 16; o > 0; o >>= 1) {
                emn = fminf(emn, __shfl_xor_sync(0xffffffffu, emn, o));
                emx = fmaxf(emx, __shfl_xor_sync(0xffffffffu, emx, o));
            }
            int w = t >> 5;
            if ((t & 31) == 0) { red[0][w] = emn; red[1][w] = emx; }
            __syncthreads();
            if (t == 0) {
                float a = red[0][0], b = red[1][0];
                #pragma unroll
                for (int i = 1; i < 8; i++) {
                    a = fminf(a, red[0][i]); b = fmaxf(b, red[1][i]);
                }
                if (type == 1 && sl != 2) { a = fwd_y(a, sl); b = fwd_y(b, sl); }
                mnmx[0] = a; mnmx[1] = b;
            }
        }
        __syncthreads();

        float mn = mnmx[0], mx = mnmx[1];
        float span = mx - mn;

        // ---- 4 consecutive grid points per thread ----
        float u[4], lf[4];
        float umn =  INFINITY, umx = -INFINITY;
        #pragma unroll
        for (int i = 0; i < 4; i++) {
            int j = 4 * t + i;
            float frac = (float)j / 1023.0f;
            float tg = mn + span * frac;
            if (tg == 0.0f) tg = 1e-7f;
            float xi, l;
            if (type == 0) { xi = tg; l = 1.0f; }
            else {
                switch (sl) {
                    case 0: xi = tg * 0.5f;          l = 0.5f;  break;
                    case 1: xi = tg + 3.0f;          l = 1.0f;  break;
                    case 2: xi = 1.0f / tg;          l = 1.0f / (tg * tg); break;
                    case 3: xi = (tg - 5.0f) / 0.8f; l = 1.25f; break;
                    case 4: {
                        float yc = fminf(fmaxf(tg, 1e-6f), 1.0f - 1e-6f);
                        xi = logf(yc) - log1pf(-yc);
                        l  = 1.0f / (yc * (1.0f - yc));
                        break;
                    }
                    default: {
                        float yp = fmaxf(tg, 1e-6f);
                        float em = expm1f(yp);
                        xi = logf(em);
                        l  = 1.0f / (-expm1f(-yp));
                        break;
                    }
                }
            }
            float uv = xi * KSCALE;
            u[i]  = uv;
            lf[i] = l;
            umn = fminf(umn, uv);
            umx = fmaxf(umx, uv);
        }

        // ---- warp-union window bounds ----
        #pragma unroll
        for (int o = 16; o > 0; o >>= 1) {
            umn = fminf(umn, __shfl_xor_sync(0xffffffffu, umn, o));
            umx = fmaxf(umx, __shfl_xor_sync(0xffffffffu, umx, o));
        }
        float lowv  = umn - CUT;
        float highv = umx + CUT;

        // ---- pdf loop: warp-uniform skip over unsorted basis ----
        float a0 = 0.f, a1 = 0.f, a2 = 0.f, a3 = 0.f;
        #pragma unroll 4
        for (int b = 0; b < NBASIS; b++) {
            float xv = xsK[b];                   // broadcast LDS, warp-uniform
            if (xv >= lowv && xv <= highv) {
                float d0 = u[0] - xv;
                float d1 = u[1] - xv;
                float d2 = u[2] - xv;
                float d3 = u[3] - xv;
                a0 += ex2f_raw(-d0 * d0);
                a1 += ex2f_raw(-d1 * d1);
                a2 += ex2f_raw(-d2 * d2);
                a3 += ex2f_raw(-d3 * d3);
            }
        }

        if (slot_idx != type) {
            float4 v;
            v.x = (a0 == 0.f) ? 0.f : a0 * INV_NORM * lf[0];
            v.y = (a1 == 0.f) ? 0.f : a1 * INV_NORM * lf[1];
            v.z = (a2 == 0.f) ? 0.f : a2 * INV_NORM * lf[2];
            v.w = (a3 == 0.f) ? 0.f : a3 * INV_NORM * lf[3];
            float4* dst = (float4*)(out + (size_t)type * SLOT_ELEMS + (size_t)row * RGRID);
            dst[t] = v;
        }
    } else {
        // ---------- copy branch: one contiguous chunk per block ----------
        int cb = bid >> 1;          // 0..1023
        int s  = cb >> 3;           // slot 0..127 (8 blocks per slot)
        int srcs;
        if (s == slot_idx)      srcs = 0;      // out[slot_idx] = prev = bank[0]
        else if (s < 2)         return;        // slots 0/1 written by compute blocks
        else                    srcs = s;

        long coff = (long)(cb & 7) * CHUNK4;
        const float4* __restrict__ src = (const float4*)bank + (long)srcs * SLOT4 + coff;
        float4*       __restrict__ dst = (float4*)out        + (long)s    * SLOT4 + coff;

        #pragma unroll 8
        for (int i = t; i < CHUNK4; i += 256) {
            dst[i] = src[i];
        }
    }
}

extern "C" void kernel_launch(void* const* d_in, const int* in_sizes, int n_in,
                              void* d_out, int out_size)
{
    const float* inputs   = (const float*)d_in[0];
    const float* bank     = (const float*)d_in[1];
    const float* noise    = (const float*)d_in[2];
    const int*   comp_idx = (const int*)  d_in[3];
    const int*   sel      = (const int*)  d_in[4];
    const int*   slot_p   = (n_in >= 6) ? (const int*)d_in[5] : nullptr;
    float* out = (float*)d_out;

    main_kernel<<<2048, 256>>>(inputs, bank, noise, comp_idx, sel, slot_p, out);
}